// round 3
// baseline (speedup 1.0000x reference)
#include <cuda_runtime.h>
#include <cuda_bf16.h>

#define ND        128
#define MAXN      50016
#define MAXE      1600000
#define MAXG      80

// -------- device scratch (no allocation allowed) --------
__device__ float g_deg[MAXN];
__device__ float g_dinv[MAXN];
__device__ int   g_cnt[MAXN];
__device__ int   g_rowptr[MAXN + 1];
__device__ int   g_fill[MAXN];
__device__ int   g_col[MAXE];
__device__ float g_val[MAXE];
__device__ float g_bufA[50000 * ND];
__device__ float g_bufB[50000 * ND];
__device__ int   g_gstart[MAXG + 1];

// -------- degree init: self-loop weight 1 --------
__global__ void k_init(int n) {
    int i = blockIdx.x * blockDim.x + threadIdx.x;
    if (i < n) { g_deg[i] = 1.0f; g_cnt[i] = 0; }
}

// -------- degree + per-dst edge count --------
__global__ void k_deg(const int* __restrict__ dst, const float* __restrict__ ew, int E) {
    int e = blockIdx.x * blockDim.x + threadIdx.x;
    if (e < E) {
        int d = dst[e];
        atomicAdd(&g_deg[d], ew[e]);
        atomicAdd(&g_cnt[d], 1);
    }
}

__global__ void k_dinv(int n) {
    int i = blockIdx.x * blockDim.x + threadIdx.x;
    if (i < n) {
        float d = g_deg[i];
        g_dinv[i] = (d > 0.0f) ? rsqrtf(d) : 0.0f;
    }
}

// -------- single-block exclusive scan of g_cnt -> g_rowptr --------
__global__ void k_scan(int n) {
    __shared__ int warp_sums[32];
    __shared__ int s_carry;
    int tid = threadIdx.x;
    int lane = tid & 31, wid = tid >> 5;
    if (tid == 0) s_carry = 0;
    __syncthreads();
    for (int base = 0; base < n; base += 1024) {
        int i = base + tid;
        int v = (i < n) ? g_cnt[i] : 0;
        int x = v;
        #pragma unroll
        for (int o = 1; o < 32; o <<= 1) {
            int y = __shfl_up_sync(0xFFFFFFFFu, x, o);
            if (lane >= o) x += y;
        }
        if (lane == 31) warp_sums[wid] = x;
        __syncthreads();
        if (wid == 0) {
            int w = warp_sums[lane];
            #pragma unroll
            for (int o = 1; o < 32; o <<= 1) {
                int y = __shfl_up_sync(0xFFFFFFFFu, w, o);
                if (lane >= o) w += y;
            }
            warp_sums[lane] = w;
        }
        __syncthreads();
        int incl = x + (wid > 0 ? warp_sums[wid - 1] : 0) + s_carry;
        if (i < n) g_rowptr[i + 1] = incl;
        __syncthreads();
        if (tid == 0) s_carry += warp_sums[31];
        __syncthreads();
    }
    if (threadIdx.x == 0) g_rowptr[0] = 0;
}

__global__ void k_fillinit(int n) {
    int i = blockIdx.x * blockDim.x + threadIdx.x;
    if (i < n) g_fill[i] = g_rowptr[i];
}

// -------- scatter edges into CSR (by dst), with precomputed norm --------
__global__ void k_csr(const int* __restrict__ src, const int* __restrict__ dst,
                      const float* __restrict__ ew, int E) {
    int e = blockIdx.x * blockDim.x + threadIdx.x;
    if (e < E) {
        int s = src[e], d = dst[e];
        int p = atomicAdd(&g_fill[d], 1);
        g_col[p] = s;
        g_val[p] = g_dinv[s] * ew[e] * g_dinv[d];
    }
}

// -------- fp32 GEMM: Y[n,128] = X[n,128] @ W[128,128] --------
// 256 threads, 64-row tile, each thread 8x4 micro-tile, K chunked by 32.
__global__ void __launch_bounds__(256) k_gemm(const float* __restrict__ X,
                                              const float* __restrict__ W,
                                              float* __restrict__ Y, int n) {
    __shared__ __align__(16) float Ws[32][128];
    __shared__ __align__(16) float Xs[32][68];
    const int tx = threadIdx.x & 31;   // n-group (4 cols)
    const int ty = threadIdx.x >> 5;   // m-group (8 rows)
    const int row0 = blockIdx.x * 64;
    float acc[8][4];
    #pragma unroll
    for (int i = 0; i < 8; i++)
        #pragma unroll
        for (int j = 0; j < 4; j++) acc[i][j] = 0.0f;

    for (int kc = 0; kc < ND; kc += 32) {
        // W rows kc..kc+31 are contiguous: 4096 floats = 1024 float4
        {
            const float4* srcp = reinterpret_cast<const float4*>(W + kc * ND);
            float4* dstp = reinterpret_cast<float4*>(&Ws[0][0]);
            #pragma unroll
            for (int i = 0; i < 4; i++)
                dstp[threadIdx.x + i * 256] = srcp[threadIdx.x + i * 256];
        }
        // X chunk transposed into Xs[k][m]
        #pragma unroll
        for (int i = 0; i < 2; i++) {
            int idx = threadIdx.x + i * 256;     // 0..511
            int m  = idx >> 3;                   // 0..63
            int kv = idx & 7;                    // 0..7 (float4 within 32 k)
            int row = row0 + m;
            float4 v = make_float4(0.f, 0.f, 0.f, 0.f);
            if (row < n)
                v = *reinterpret_cast<const float4*>(X + row * ND + kc + kv * 4);
            Xs[kv * 4 + 0][m] = v.x;
            Xs[kv * 4 + 1][m] = v.y;
            Xs[kv * 4 + 2][m] = v.z;
            Xs[kv * 4 + 3][m] = v.w;
        }
        __syncthreads();
        #pragma unroll
        for (int k = 0; k < 32; k++) {
            float4 b  = *reinterpret_cast<const float4*>(&Ws[k][tx * 4]);
            float4 a0 = *reinterpret_cast<const float4*>(&Xs[k][ty * 8]);
            float4 a1 = *reinterpret_cast<const float4*>(&Xs[k][ty * 8 + 4]);
            float am[8] = {a0.x, a0.y, a0.z, a0.w, a1.x, a1.y, a1.z, a1.w};
            #pragma unroll
            for (int mi = 0; mi < 8; mi++) {
                acc[mi][0] = fmaf(am[mi], b.x, acc[mi][0]);
                acc[mi][1] = fmaf(am[mi], b.y, acc[mi][1]);
                acc[mi][2] = fmaf(am[mi], b.z, acc[mi][2]);
                acc[mi][3] = fmaf(am[mi], b.w, acc[mi][3]);
            }
        }
        __syncthreads();
    }
    #pragma unroll
    for (int mi = 0; mi < 8; mi++) {
        int row = row0 + ty * 8 + mi;
        if (row < n)
            *reinterpret_cast<float4*>(Y + row * ND + tx * 4) =
                make_float4(acc[mi][0], acc[mi][1], acc[mi][2], acc[mi][3]);
    }
}

// -------- CSR pull aggregation: one warp per node, float4 per lane --------
__global__ void __launch_bounds__(256) k_agg(const float4* __restrict__ XW,
                                             const float* __restrict__ bias,
                                             float4* __restrict__ OUT,
                                             int n, int relu) {
    int node = (blockIdx.x * blockDim.x + threadIdx.x) >> 5;
    int lane = threadIdx.x & 31;
    if (node >= n) return;

    float di = g_dinv[node];
    float sl = di * di;                        // self-loop norm
    float4 a = XW[node * 32 + lane];
    float4 acc = make_float4(a.x * sl, a.y * sl, a.z * sl, a.w * sl);

    int e0 = g_rowptr[node], e1 = g_rowptr[node + 1];
    int e = e0;
    for (; e + 4 <= e1; e += 4) {
        int   c0 = g_col[e],     c1 = g_col[e + 1];
        int   c2 = g_col[e + 2], c3 = g_col[e + 3];
        float v0 = g_val[e],     v1 = g_val[e + 1];
        float v2 = g_val[e + 2], v3 = g_val[e + 3];
        float4 m0 = XW[c0 * 32 + lane];
        float4 m1 = XW[c1 * 32 + lane];
        float4 m2 = XW[c2 * 32 + lane];
        float4 m3 = XW[c3 * 32 + lane];
        acc.x = fmaf(v0, m0.x, acc.x); acc.y = fmaf(v0, m0.y, acc.y);
        acc.z = fmaf(v0, m0.z, acc.z); acc.w = fmaf(v0, m0.w, acc.w);
        acc.x = fmaf(v1, m1.x, acc.x); acc.y = fmaf(v1, m1.y, acc.y);
        acc.z = fmaf(v1, m1.z, acc.z); acc.w = fmaf(v1, m1.w, acc.w);
        acc.x = fmaf(v2, m2.x, acc.x); acc.y = fmaf(v2, m2.y, acc.y);
        acc.z = fmaf(v2, m2.z, acc.z); acc.w = fmaf(v2, m2.w, acc.w);
        acc.x = fmaf(v3, m3.x, acc.x); acc.y = fmaf(v3, m3.y, acc.y);
        acc.z = fmaf(v3, m3.z, acc.z); acc.w = fmaf(v3, m3.w, acc.w);
    }
    for (; e < e1; e++) {
        int c = g_col[e];
        float v = g_val[e];
        float4 m = XW[c * 32 + lane];
        acc.x = fmaf(v, m.x, acc.x); acc.y = fmaf(v, m.y, acc.y);
        acc.z = fmaf(v, m.z, acc.z); acc.w = fmaf(v, m.w, acc.w);
    }
    float4 b = reinterpret_cast<const float4*>(bias)[lane];
    acc.x += b.x; acc.y += b.y; acc.z += b.z; acc.w += b.w;
    if (relu) {
        acc.x = fmaxf(acc.x, 0.f); acc.y = fmaxf(acc.y, 0.f);
        acc.z = fmaxf(acc.z, 0.f); acc.w = fmaxf(acc.w, 0.f);
    }
    OUT[node * 32 + lane] = acc;
}

// -------- graph segment bounds: batch is sorted -> binary search --------
__global__ void k_bounds(const int* __restrict__ batch, int n, int ngraphs) {
    int g = threadIdx.x;
    if (g > ngraphs) return;
    int lo = 0, hi = n;
    while (lo < hi) {
        int mid = (lo + hi) >> 1;
        if (batch[mid] < g) lo = mid + 1; else hi = mid;
    }
    g_gstart[g] = lo;
}

// -------- global mean pool: one block per graph --------
__global__ void k_pool(const float* __restrict__ h, float* __restrict__ out) {
    int g = blockIdx.x;
    int t = threadIdx.x;   // 0..127
    int s = g_gstart[g], e = g_gstart[g + 1];
    float acc = 0.0f;
    for (int i = s; i < e; i++) acc += h[i * ND + t];
    int cnt = e - s;
    float denom = (float)(cnt > 0 ? cnt : 1);
    out[g * ND + t] = acc / denom;
}

extern "C" void kernel_launch(void* const* d_in, const int* in_sizes, int n_in,
                              void* d_out, int out_size) {
    const float* x     = (const float*)d_in[0];
    const int*   ei    = (const int*)d_in[1];
    const float* ew    = (const float*)d_in[2];
    const int*   batch = (const int*)d_in[3];
    const float* W0    = (const float*)d_in[4];
    const float* b0    = (const float*)d_in[5];
    const float* W1    = (const float*)d_in[6];
    const float* b1    = (const float*)d_in[7];
    const float* W2    = (const float*)d_in[8];
    const float* b2    = (const float*)d_in[9];

    int n = in_sizes[0] / ND;
    int E = in_sizes[1] / 2;
    int ngraphs = out_size / ND;
    const int* src = ei;
    const int* dst = ei + E;

    float *bufA, *bufB;
    cudaGetSymbolAddress((void**)&bufA, g_bufA);
    cudaGetSymbolAddress((void**)&bufB, g_bufB);

    int nb = (n + 255) / 256;
    int eb = (E + 255) / 256;
    int gb = (n + 63) / 64;
    int ab = (int)(((long long)n * 32 + 255) / 256);

    // normalization + CSR build (once per launch)
    k_init<<<nb, 256>>>(n);
    k_deg<<<eb, 256>>>(dst, ew, E);
    k_dinv<<<nb, 256>>>(n);
    k_scan<<<1, 1024>>>(n);
    k_fillinit<<<nb, 256>>>(n);
    k_csr<<<eb, 256>>>(src, dst, ew, E);

    // layer 0
    k_gemm<<<gb, 256>>>(x, W0, bufA, n);
    k_agg<<<ab, 256>>>((const float4*)bufA, b0, (float4*)bufB, n, 1);
    // layer 1
    k_gemm<<<gb, 256>>>(bufB, W1, bufA, n);
    k_agg<<<ab, 256>>>((const float4*)bufA, b1, (float4*)bufB, n, 1);
    // layer 2
    k_gemm<<<gb, 256>>>(bufB, W2, bufA, n);
    k_agg<<<ab, 256>>>((const float4*)bufA, b2, (float4*)bufB, n, 0);

    // pooling
    k_bounds<<<1, 128>>>(batch, n, ngraphs);
    k_pool<<<ngraphs, 128>>>(bufB, (float*)d_out);
}

// round 4
// speedup vs baseline: 1.2067x; 1.2067x over previous
#include <cuda_runtime.h>
#include <cuda_fp16.h>

#define ND        128
#define MAXN      50016
#define MAXE      1600000
#define MAXG      80
#define SCANB     1024
#define MAXBLK    64          // ceil(MAXN/SCANB)

// -------- device scratch (no allocation allowed) --------
__device__ float g_deg[MAXN];
__device__ float g_dinv[MAXN];
__device__ int   g_cnt[MAXN];
__device__ int   g_rowptr[MAXN + 1];
__device__ int   g_fill[MAXN];
__device__ int   g_bsum[MAXBLK];
__device__ int   g_boff[MAXBLK];
__device__ int   g_col[MAXE];
__device__ float g_val[MAXE];
__device__ float  g_bufA[50000 * ND];   // fp32: agg output / gemm input
__device__ __half g_bufH[50000 * ND];   // fp16: gemm output (messages)
__device__ int   g_gstart[MAXG + 1];

// -------- degree init: self-loop weight 1 --------
__global__ void k_init(int n) {
    int i = blockIdx.x * blockDim.x + threadIdx.x;
    if (i < n) { g_deg[i] = 1.0f; g_cnt[i] = 0; }
}

// -------- degree + per-dst edge count --------
__global__ void k_deg(const int* __restrict__ dst, const float* __restrict__ ew, int E) {
    int e = blockIdx.x * blockDim.x + threadIdx.x;
    if (e < E) {
        int d = dst[e];
        atomicAdd(&g_deg[d], ew[e]);
        atomicAdd(&g_cnt[d], 1);
    }
}

__global__ void k_dinv(int n) {
    int i = blockIdx.x * blockDim.x + threadIdx.x;
    if (i < n) {
        float d = g_deg[i];
        g_dinv[i] = (d > 0.0f) ? rsqrtf(d) : 0.0f;
    }
}

// -------- multi-block scan, phase A: block-local inclusive scan --------
__global__ void k_scanA(int n) {
    __shared__ int warp_sums[32];
    int tid = threadIdx.x;
    int lane = tid & 31, wid = tid >> 5;
    int i = blockIdx.x * SCANB + tid;
    int x = (i < n) ? g_cnt[i] : 0;
    #pragma unroll
    for (int o = 1; o < 32; o <<= 1) {
        int y = __shfl_up_sync(0xFFFFFFFFu, x, o);
        if (lane >= o) x += y;
    }
    if (lane == 31) warp_sums[wid] = x;
    __syncthreads();
    if (wid == 0) {
        int w = warp_sums[lane];
        #pragma unroll
        for (int o = 1; o < 32; o <<= 1) {
            int y = __shfl_up_sync(0xFFFFFFFFu, w, o);
            if (lane >= o) w += y;
        }
        warp_sums[lane] = w;
    }
    __syncthreads();
    int incl = x + (wid > 0 ? warp_sums[wid - 1] : 0);
    if (i < n) g_rowptr[i + 1] = incl;          // partial (pre-offset)
    if (tid == SCANB - 1) g_bsum[blockIdx.x] = incl;
}

// -------- phase B: exclusive scan of block sums (<=64) --------
__global__ void k_scanB(int nblk) {
    int tid = threadIdx.x;   // 64 threads
    int v = (tid < nblk) ? g_bsum[tid] : 0;
    int x = v;
    #pragma unroll
    for (int o = 1; o < 32; o <<= 1) {
        int y = __shfl_up_sync(0xFFFFFFFFu, x, o);
        if ((tid & 31) >= o) x += y;
    }
    __shared__ int w0;
    if (tid == 31) w0 = x;
    __syncthreads();
    if (tid >= 32) x += w0;
    if (tid < nblk) g_boff[tid] = x - v;        // exclusive
}

// -------- phase C: add offsets + init g_fill --------
__global__ void k_scanC(int n) {
    int i = blockIdx.x * SCANB + threadIdx.x;
    if (i < n) {
        int r = g_rowptr[i + 1] + g_boff[blockIdx.x];
        g_rowptr[i + 1] = r;
        if (i + 1 < n) g_fill[i + 1] = r;
    }
    if (i == 0) { g_rowptr[0] = 0; g_fill[0] = 0; }
}

// -------- scatter edges into CSR (by dst), with precomputed norm --------
__global__ void k_csr(const int* __restrict__ src, const int* __restrict__ dst,
                      const float* __restrict__ ew, int E) {
    int e = blockIdx.x * blockDim.x + threadIdx.x;
    if (e < E) {
        int s = src[e], d = dst[e];
        int p = atomicAdd(&g_fill[d], 1);
        g_col[p] = s;
        g_val[p] = g_dinv[s] * ew[e] * g_dinv[d];
    }
}

// -------- fp32 GEMM: H[n,128] = X[n,128] @ W[128,128], fp16 output --------
__global__ void __launch_bounds__(256) k_gemm(const float* __restrict__ X,
                                              const float* __restrict__ W,
                                              __half* __restrict__ Y, int n) {
    __shared__ __align__(16) float Ws[32][128];
    __shared__ __align__(16) float Xs[32][68];
    const int tx = threadIdx.x & 31;   // n-group (4 cols)
    const int ty = threadIdx.x >> 5;   // m-group (8 rows)
    const int row0 = blockIdx.x * 64;
    float acc[8][4];
    #pragma unroll
    for (int i = 0; i < 8; i++)
        #pragma unroll
        for (int j = 0; j < 4; j++) acc[i][j] = 0.0f;

    for (int kc = 0; kc < ND; kc += 32) {
        {
            const float4* srcp = reinterpret_cast<const float4*>(W + kc * ND);
            float4* dstp = reinterpret_cast<float4*>(&Ws[0][0]);
            #pragma unroll
            for (int i = 0; i < 4; i++)
                dstp[threadIdx.x + i * 256] = srcp[threadIdx.x + i * 256];
        }
        #pragma unroll
        for (int i = 0; i < 2; i++) {
            int idx = threadIdx.x + i * 256;
            int m  = idx >> 3;
            int kv = idx & 7;
            int row = row0 + m;
            float4 v = make_float4(0.f, 0.f, 0.f, 0.f);
            if (row < n)
                v = *reinterpret_cast<const float4*>(X + row * ND + kc + kv * 4);
            Xs[kv * 4 + 0][m] = v.x;
            Xs[kv * 4 + 1][m] = v.y;
            Xs[kv * 4 + 2][m] = v.z;
            Xs[kv * 4 + 3][m] = v.w;
        }
        __syncthreads();
        #pragma unroll
        for (int k = 0; k < 32; k++) {
            float4 b  = *reinterpret_cast<const float4*>(&Ws[k][tx * 4]);
            float4 a0 = *reinterpret_cast<const float4*>(&Xs[k][ty * 8]);
            float4 a1 = *reinterpret_cast<const float4*>(&Xs[k][ty * 8 + 4]);
            float am[8] = {a0.x, a0.y, a0.z, a0.w, a1.x, a1.y, a1.z, a1.w};
            #pragma unroll
            for (int mi = 0; mi < 8; mi++) {
                acc[mi][0] = fmaf(am[mi], b.x, acc[mi][0]);
                acc[mi][1] = fmaf(am[mi], b.y, acc[mi][1]);
                acc[mi][2] = fmaf(am[mi], b.z, acc[mi][2]);
                acc[mi][3] = fmaf(am[mi], b.w, acc[mi][3]);
            }
        }
        __syncthreads();
    }
    #pragma unroll
    for (int mi = 0; mi < 8; mi++) {
        int row = row0 + ty * 8 + mi;
        if (row < n) {
            __half2 h0 = __floats2half2_rn(acc[mi][0], acc[mi][1]);
            __half2 h1 = __floats2half2_rn(acc[mi][2], acc[mi][3]);
            uint2 u;
            u.x = *reinterpret_cast<unsigned int*>(&h0);
            u.y = *reinterpret_cast<unsigned int*>(&h1);
            *reinterpret_cast<uint2*>(Y + row * ND + tx * 4) = u;
        }
    }
}

__device__ __forceinline__ float4 h4_to_f4(uint2 u) {
    __half2 a = *reinterpret_cast<__half2*>(&u.x);
    __half2 b = *reinterpret_cast<__half2*>(&u.y);
    float2 fa = __half22float2(a);
    float2 fb = __half22float2(b);
    return make_float4(fa.x, fa.y, fb.x, fb.y);
}

// -------- CSR pull aggregation: warp per node, fp16 gather, fp32 accum --------
__global__ void __launch_bounds__(256) k_agg(const __half* __restrict__ XW,
                                             const float* __restrict__ bias,
                                             float4* __restrict__ OUT,
                                             int n, int relu) {
    int node = (blockIdx.x * blockDim.x + threadIdx.x) >> 5;
    int lane = threadIdx.x & 31;
    if (node >= n) return;

    const uint2* XWv = reinterpret_cast<const uint2*>(XW);

    float di = g_dinv[node];
    float sl = di * di;                        // self-loop norm
    float4 a = h4_to_f4(XWv[node * 32 + lane]);
    float4 acc = make_float4(a.x * sl, a.y * sl, a.z * sl, a.w * sl);

    int e0 = g_rowptr[node], e1 = g_rowptr[node + 1];
    int e = e0;
    for (; e + 4 <= e1; e += 4) {
        int   c0 = g_col[e],     c1 = g_col[e + 1];
        int   c2 = g_col[e + 2], c3 = g_col[e + 3];
        float v0 = g_val[e],     v1 = g_val[e + 1];
        float v2 = g_val[e + 2], v3 = g_val[e + 3];
        uint2 u0 = XWv[c0 * 32 + lane];
        uint2 u1 = XWv[c1 * 32 + lane];
        uint2 u2 = XWv[c2 * 32 + lane];
        uint2 u3 = XWv[c3 * 32 + lane];
        float4 m0 = h4_to_f4(u0);
        float4 m1 = h4_to_f4(u1);
        float4 m2 = h4_to_f4(u2);
        float4 m3 = h4_to_f4(u3);
        acc.x = fmaf(v0, m0.x, acc.x); acc.y = fmaf(v0, m0.y, acc.y);
        acc.z = fmaf(v0, m0.z, acc.z); acc.w = fmaf(v0, m0.w, acc.w);
        acc.x = fmaf(v1, m1.x, acc.x); acc.y = fmaf(v1, m1.y, acc.y);
        acc.z = fmaf(v1, m1.z, acc.z); acc.w = fmaf(v1, m1.w, acc.w);
        acc.x = fmaf(v2, m2.x, acc.x); acc.y = fmaf(v2, m2.y, acc.y);
        acc.z = fmaf(v2, m2.z, acc.z); acc.w = fmaf(v2, m2.w, acc.w);
        acc.x = fmaf(v3, m3.x, acc.x); acc.y = fmaf(v3, m3.y, acc.y);
        acc.z = fmaf(v3, m3.z, acc.z); acc.w = fmaf(v3, m3.w, acc.w);
    }
    for (; e < e1; e++) {
        int c = g_col[e];
        float v = g_val[e];
        float4 m = h4_to_f4(XWv[c * 32 + lane]);
        acc.x = fmaf(v, m.x, acc.x); acc.y = fmaf(v, m.y, acc.y);
        acc.z = fmaf(v, m.z, acc.z); acc.w = fmaf(v, m.w, acc.w);
    }
    float4 b = reinterpret_cast<const float4*>(bias)[lane];
    acc.x += b.x; acc.y += b.y; acc.z += b.z; acc.w += b.w;
    if (relu) {
        acc.x = fmaxf(acc.x, 0.f); acc.y = fmaxf(acc.y, 0.f);
        acc.z = fmaxf(acc.z, 0.f); acc.w = fmaxf(acc.w, 0.f);
    }
    OUT[node * 32 + lane] = acc;
}

// -------- graph segment bounds: batch is sorted -> binary search --------
__global__ void k_bounds(const int* __restrict__ batch, int n, int ngraphs) {
    int g = threadIdx.x;
    if (g > ngraphs) return;
    int lo = 0, hi = n;
    while (lo < hi) {
        int mid = (lo + hi) >> 1;
        if (batch[mid] < g) lo = mid + 1; else hi = mid;
    }
    g_gstart[g] = lo;
}

// -------- global mean pool: one block per graph --------
__global__ void k_pool(const float* __restrict__ h, float* __restrict__ out) {
    int g = blockIdx.x;
    int t = threadIdx.x;   // 0..127
    int s = g_gstart[g], e = g_gstart[g + 1];
    float acc = 0.0f;
    for (int i = s; i < e; i++) acc += h[i * ND + t];
    int cnt = e - s;
    float denom = (float)(cnt > 0 ? cnt : 1);
    out[g * ND + t] = acc / denom;
}

extern "C" void kernel_launch(void* const* d_in, const int* in_sizes, int n_in,
                              void* d_out, int out_size) {
    const float* x     = (const float*)d_in[0];
    const int*   ei    = (const int*)d_in[1];
    const float* ew    = (const float*)d_in[2];
    const int*   batch = (const int*)d_in[3];
    const float* W0    = (const float*)d_in[4];
    const float* b0    = (const float*)d_in[5];
    const float* W1    = (const float*)d_in[6];
    const float* b1    = (const float*)d_in[7];
    const float* W2    = (const float*)d_in[8];
    const float* b2    = (const float*)d_in[9];

    int n = in_sizes[0] / ND;
    int E = in_sizes[1] / 2;
    int ngraphs = out_size / ND;
    const int* src = ei;
    const int* dst = ei + E;

    float  *bufA;
    __half *bufH;
    cudaGetSymbolAddress((void**)&bufA, g_bufA);
    cudaGetSymbolAddress((void**)&bufH, g_bufH);

    int nb  = (n + 255) / 256;
    int eb  = (E + 255) / 256;
    int gb  = (n + 63) / 64;
    int ab  = (int)(((long long)n * 32 + 255) / 256);
    int sbk = (n + SCANB - 1) / SCANB;

    // normalization + CSR build (once per launch)
    k_init<<<nb, 256>>>(n);
    k_deg<<<eb, 256>>>(dst, ew, E);
    k_dinv<<<nb, 256>>>(n);
    k_scanA<<<sbk, SCANB>>>(n);
    k_scanB<<<1, 64>>>(sbk);
    k_scanC<<<sbk, SCANB>>>(n);
    k_csr<<<eb, 256>>>(src, dst, ew, E);

    // layer 0
    k_gemm<<<gb, 256>>>(x, W0, bufH, n);
    k_agg<<<ab, 256>>>(bufH, b0, (float4*)bufA, n, 1);
    // layer 1
    k_gemm<<<gb, 256>>>(bufA, W1, bufH, n);
    k_agg<<<ab, 256>>>(bufH, b1, (float4*)bufA, n, 1);
    // layer 2
    k_gemm<<<gb, 256>>>(bufA, W2, bufH, n);
    k_agg<<<ab, 256>>>(bufH, b2, (float4*)bufA, n, 0);

    // pooling
    k_bounds<<<1, 128>>>(batch, n, ngraphs);
    k_pool<<<ngraphs, 128>>>(bufA, (float*)d_out);
}

// round 5
// speedup vs baseline: 1.4570x; 1.2074x over previous
#include <cuda_runtime.h>
#include <cuda_fp16.h>

#define ND        128
#define MAXN      50016
#define MAXE      1600000
#define MAXG      80
#define SCANB     1024
#define MAXBLK    64

// -------- device scratch (no allocation allowed) --------
__device__ float g_deg[MAXN];
__device__ float g_dinv[MAXN];
__device__ int   g_cnt[MAXN];
__device__ int   g_rowptr[MAXN + 1];
__device__ int   g_fill[MAXN];
__device__ int   g_bsum[MAXBLK];
__device__ int   g_boff[MAXBLK];
__device__ int   g_col[MAXE];
__device__ float g_val[MAXE];
__device__ float  g_bufA[50000 * ND];   // fp32: agg output / gemm input
__device__ __half g_bufH[50000 * ND];   // fp16: gemm output (messages)
__device__ int   g_gstart[MAXG + 1];

__device__ __forceinline__ unsigned tf32_of(float f) {
    unsigned u;
    asm("cvt.rna.tf32.f32 %0, %1;" : "=r"(u) : "f"(f));
    return u;
}

// -------- degree init: self-loop weight 1 --------
__global__ void k_init(int n) {
    int i = blockIdx.x * blockDim.x + threadIdx.x;
    if (i < n) { g_deg[i] = 1.0f; g_cnt[i] = 0; }
}

// -------- degree + per-dst edge count --------
__global__ void k_deg(const int* __restrict__ dst, const float* __restrict__ ew, int E) {
    int e = blockIdx.x * blockDim.x + threadIdx.x;
    if (e < E) {
        int d = dst[e];
        atomicAdd(&g_deg[d], ew[e]);
        atomicAdd(&g_cnt[d], 1);
    }
}

__global__ void k_dinv(int n) {
    int i = blockIdx.x * blockDim.x + threadIdx.x;
    if (i < n) {
        float d = g_deg[i];
        g_dinv[i] = (d > 0.0f) ? rsqrtf(d) : 0.0f;
    }
}

// -------- multi-block scan, phase A: block-local inclusive scan --------
__global__ void k_scanA(int n) {
    __shared__ int warp_sums[32];
    int tid = threadIdx.x;
    int lane = tid & 31, wid = tid >> 5;
    int i = blockIdx.x * SCANB + tid;
    int x = (i < n) ? g_cnt[i] : 0;
    #pragma unroll
    for (int o = 1; o < 32; o <<= 1) {
        int y = __shfl_up_sync(0xFFFFFFFFu, x, o);
        if (lane >= o) x += y;
    }
    if (lane == 31) warp_sums[wid] = x;
    __syncthreads();
    if (wid == 0) {
        int w = warp_sums[lane];
        #pragma unroll
        for (int o = 1; o < 32; o <<= 1) {
            int y = __shfl_up_sync(0xFFFFFFFFu, w, o);
            if (lane >= o) w += y;
        }
        warp_sums[lane] = w;
    }
    __syncthreads();
    int incl = x + (wid > 0 ? warp_sums[wid - 1] : 0);
    if (i < n) g_rowptr[i + 1] = incl;
    if (tid == SCANB - 1) g_bsum[blockIdx.x] = incl;
}

// -------- phase B: exclusive scan of block sums (<=64) --------
__global__ void k_scanB(int nblk) {
    int tid = threadIdx.x;
    int v = (tid < nblk) ? g_bsum[tid] : 0;
    int x = v;
    #pragma unroll
    for (int o = 1; o < 32; o <<= 1) {
        int y = __shfl_up_sync(0xFFFFFFFFu, x, o);
        if ((tid & 31) >= o) x += y;
    }
    __shared__ int w0;
    if (tid == 31) w0 = x;
    __syncthreads();
    if (tid >= 32) x += w0;
    if (tid < nblk) g_boff[tid] = x - v;
}

// -------- phase C: add offsets + init g_fill --------
__global__ void k_scanC(int n) {
    int i = blockIdx.x * SCANB + threadIdx.x;
    if (i < n) {
        int r = g_rowptr[i + 1] + g_boff[blockIdx.x];
        g_rowptr[i + 1] = r;
        if (i + 1 < n) g_fill[i + 1] = r;
    }
    if (i == 0) { g_rowptr[0] = 0; g_fill[0] = 0; }
}

// -------- scatter edges into CSR (by dst), with precomputed norm --------
__global__ void k_csr(const int* __restrict__ src, const int* __restrict__ dst,
                      const float* __restrict__ ew, int E) {
    int e = blockIdx.x * blockDim.x + threadIdx.x;
    if (e < E) {
        int s = src[e], d = dst[e];
        int p = atomicAdd(&g_fill[d], 1);
        g_col[p] = s;
        g_val[p] = g_dinv[s] * ew[e] * g_dinv[d];
    }
}

// -------- tf32 tensor-core GEMM: H[n,128] = X[n,128] @ W[128,128], fp16 out --
// 256 threads = 8 warps; block tile 128 rows x 128 cols; K chunked by 32.
// Each warp: 16 rows x 128 cols via mma.sync.m16n8k8.tf32 (16 n-tiles).
__global__ void __launch_bounds__(256) k_gemm(const float* __restrict__ X,
                                              const float* __restrict__ W,
                                              __half* __restrict__ Y, int n) {
    __shared__ unsigned Xs[128][36];   // [row][k], pitch 36 -> conflict-free frags
    __shared__ unsigned Ws[32][136];   // [k][col], pitch 136 -> conflict-free frags
    const int tid  = threadIdx.x;
    const int warp = tid >> 5, lane = tid & 31;
    const int gid  = lane >> 2, tig = lane & 3;
    const int row0 = blockIdx.x * 128;
    const int wr   = warp * 16;

    float acc[16][4];
    #pragma unroll
    for (int t = 0; t < 16; t++)
        #pragma unroll
        for (int j = 0; j < 4; j++) acc[t][j] = 0.0f;

    for (int kc = 0; kc < ND; kc += 32) {
        // W chunk: rows kc..kc+31, 32x128 fp32, convert to tf32
        #pragma unroll
        for (int i = 0; i < 4; i++) {
            int idx = tid + i * 256;        // 0..1023 float4s
            int k   = idx >> 5;             // 0..31
            int c4  = (idx & 31) * 4;       // 0..124
            float4 v = *reinterpret_cast<const float4*>(W + (kc + k) * ND + c4);
            Ws[k][c4 + 0] = tf32_of(v.x);
            Ws[k][c4 + 1] = tf32_of(v.y);
            Ws[k][c4 + 2] = tf32_of(v.z);
            Ws[k][c4 + 3] = tf32_of(v.w);
        }
        // X chunk: rows row0..row0+127, cols kc..kc+31
        #pragma unroll
        for (int i = 0; i < 4; i++) {
            int idx = tid + i * 256;
            int m   = idx >> 3;             // 0..127
            int j4  = (idx & 7) * 4;        // 0..28
            float4 v = make_float4(0.f, 0.f, 0.f, 0.f);
            if (row0 + m < n)
                v = *reinterpret_cast<const float4*>(X + (row0 + m) * ND + kc + j4);
            Xs[m][j4 + 0] = tf32_of(v.x);
            Xs[m][j4 + 1] = tf32_of(v.y);
            Xs[m][j4 + 2] = tf32_of(v.z);
            Xs[m][j4 + 3] = tf32_of(v.w);
        }
        __syncthreads();
        #pragma unroll
        for (int ks = 0; ks < 4; ks++) {
            unsigned a0 = Xs[wr + gid    ][ks * 8 + tig];
            unsigned a1 = Xs[wr + gid + 8][ks * 8 + tig];
            unsigned a2 = Xs[wr + gid    ][ks * 8 + tig + 4];
            unsigned a3 = Xs[wr + gid + 8][ks * 8 + tig + 4];
            #pragma unroll
            for (int nt = 0; nt < 16; nt++) {
                unsigned b0 = Ws[ks * 8 + tig    ][nt * 8 + gid];
                unsigned b1 = Ws[ks * 8 + tig + 4][nt * 8 + gid];
                asm volatile(
                    "mma.sync.aligned.m16n8k8.row.col.f32.tf32.tf32.f32 "
                    "{%0,%1,%2,%3},{%4,%5,%6,%7},{%8,%9},{%0,%1,%2,%3};"
                    : "+f"(acc[nt][0]), "+f"(acc[nt][1]),
                      "+f"(acc[nt][2]), "+f"(acc[nt][3])
                    : "r"(a0), "r"(a1), "r"(a2), "r"(a3), "r"(b0), "r"(b1));
            }
        }
        __syncthreads();
    }
    // epilogue: fp16 output
    int r0 = row0 + wr + gid;
    int r1 = r0 + 8;
    #pragma unroll
    for (int nt = 0; nt < 16; nt++) {
        int col = nt * 8 + tig * 2;
        if (r0 < n)
            *reinterpret_cast<__half2*>(Y + r0 * ND + col) =
                __floats2half2_rn(acc[nt][0], acc[nt][1]);
        if (r1 < n)
            *reinterpret_cast<__half2*>(Y + r1 * ND + col) =
                __floats2half2_rn(acc[nt][2], acc[nt][3]);
    }
}

__device__ __forceinline__ float4 h4_to_f4(uint2 u) {
    __half2 a = *reinterpret_cast<__half2*>(&u.x);
    __half2 b = *reinterpret_cast<__half2*>(&u.y);
    float2 fa = __half22float2(a);
    float2 fb = __half22float2(b);
    return make_float4(fa.x, fa.y, fb.x, fb.y);
}

// -------- CSR pull aggregation: warp per node, fp16 gather, fp32 accum --------
__global__ void __launch_bounds__(256) k_agg(const __half* __restrict__ XW,
                                             const float* __restrict__ bias,
                                             float4* __restrict__ OUT,
                                             int n, int relu) {
    int node = (blockIdx.x * blockDim.x + threadIdx.x) >> 5;
    int lane = threadIdx.x & 31;
    if (node >= n) return;

    const uint2* XWv = reinterpret_cast<const uint2*>(XW);

    float di = g_dinv[node];
    float sl = di * di;
    float4 a = h4_to_f4(XWv[node * 32 + lane]);
    float4 acc = make_float4(a.x * sl, a.y * sl, a.z * sl, a.w * sl);

    int e0 = g_rowptr[node], e1 = g_rowptr[node + 1];
    int e = e0;
    for (; e + 4 <= e1; e += 4) {
        int   c0 = g_col[e],     c1 = g_col[e + 1];
        int   c2 = g_col[e + 2], c3 = g_col[e + 3];
        float v0 = g_val[e],     v1 = g_val[e + 1];
        float v2 = g_val[e + 2], v3 = g_val[e + 3];
        uint2 u0 = XWv[c0 * 32 + lane];
        uint2 u1 = XWv[c1 * 32 + lane];
        uint2 u2 = XWv[c2 * 32 + lane];
        uint2 u3 = XWv[c3 * 32 + lane];
        float4 m0 = h4_to_f4(u0);
        float4 m1 = h4_to_f4(u1);
        float4 m2 = h4_to_f4(u2);
        float4 m3 = h4_to_f4(u3);
        acc.x = fmaf(v0, m0.x, acc.x); acc.y = fmaf(v0, m0.y, acc.y);
        acc.z = fmaf(v0, m0.z, acc.z); acc.w = fmaf(v0, m0.w, acc.w);
        acc.x = fmaf(v1, m1.x, acc.x); acc.y = fmaf(v1, m1.y, acc.y);
        acc.z = fmaf(v1, m1.z, acc.z); acc.w = fmaf(v1, m1.w, acc.w);
        acc.x = fmaf(v2, m2.x, acc.x); acc.y = fmaf(v2, m2.y, acc.y);
        acc.z = fmaf(v2, m2.z, acc.z); acc.w = fmaf(v2, m2.w, acc.w);
        acc.x = fmaf(v3, m3.x, acc.x); acc.y = fmaf(v3, m3.y, acc.y);
        acc.z = fmaf(v3, m3.z, acc.z); acc.w = fmaf(v3, m3.w, acc.w);
    }
    for (; e < e1; e++) {
        int c = g_col[e];
        float v = g_val[e];
        float4 m = h4_to_f4(XWv[c * 32 + lane]);
        acc.x = fmaf(v, m.x, acc.x); acc.y = fmaf(v, m.y, acc.y);
        acc.z = fmaf(v, m.z, acc.z); acc.w = fmaf(v, m.w, acc.w);
    }
    float4 b = reinterpret_cast<const float4*>(bias)[lane];
    acc.x += b.x; acc.y += b.y; acc.z += b.z; acc.w += b.w;
    if (relu) {
        acc.x = fmaxf(acc.x, 0.f); acc.y = fmaxf(acc.y, 0.f);
        acc.z = fmaxf(acc.z, 0.f); acc.w = fmaxf(acc.w, 0.f);
    }
    OUT[node * 32 + lane] = acc;
}

// -------- graph segment bounds: batch is sorted -> binary search --------
__global__ void k_bounds(const int* __restrict__ batch, int n, int ngraphs) {
    int g = threadIdx.x;
    if (g > ngraphs) return;
    int lo = 0, hi = n;
    while (lo < hi) {
        int mid = (lo + hi) >> 1;
        if (batch[mid] < g) lo = mid + 1; else hi = mid;
    }
    g_gstart[g] = lo;
}

// -------- global mean pool: one block per graph --------
__global__ void k_pool(const float* __restrict__ h, float* __restrict__ out) {
    int g = blockIdx.x;
    int t = threadIdx.x;
    int s = g_gstart[g], e = g_gstart[g + 1];
    float acc = 0.0f;
    for (int i = s; i < e; i++) acc += h[i * ND + t];
    int cnt = e - s;
    float denom = (float)(cnt > 0 ? cnt : 1);
    out[g * ND + t] = acc / denom;
}

extern "C" void kernel_launch(void* const* d_in, const int* in_sizes, int n_in,
                              void* d_out, int out_size) {
    const float* x     = (const float*)d_in[0];
    const int*   ei    = (const int*)d_in[1];
    const float* ew    = (const float*)d_in[2];
    const int*   batch = (const int*)d_in[3];
    const float* W0    = (const float*)d_in[4];
    const float* b0    = (const float*)d_in[5];
    const float* W1    = (const float*)d_in[6];
    const float* b1    = (const float*)d_in[7];
    const float* W2    = (const float*)d_in[8];
    const float* b2    = (const float*)d_in[9];

    int n = in_sizes[0] / ND;
    int E = in_sizes[1] / 2;
    int ngraphs = out_size / ND;
    const int* src = ei;
    const int* dst = ei + E;

    float  *bufA;
    __half *bufH;
    cudaGetSymbolAddress((void**)&bufA, g_bufA);
    cudaGetSymbolAddress((void**)&bufH, g_bufH);

    int nb  = (n + 255) / 256;
    int eb  = (E + 255) / 256;
    int gb  = (n + 127) / 128;
    int ab  = (int)(((long long)n * 32 + 255) / 256);
    int sbk = (n + SCANB - 1) / SCANB;

    // normalization + CSR build
    k_init<<<nb, 256>>>(n);
    k_deg<<<eb, 256>>>(dst, ew, E);
    k_dinv<<<nb, 256>>>(n);
    k_scanA<<<sbk, SCANB>>>(n);
    k_scanB<<<1, 64>>>(sbk);
    k_scanC<<<sbk, SCANB>>>(n);
    k_csr<<<eb, 256>>>(src, dst, ew, E);

    // layer 0
    k_gemm<<<gb, 256>>>(x, W0, bufH, n);
    k_agg<<<ab, 256>>>(bufH, b0, (float4*)bufA, n, 1);
    // layer 1
    k_gemm<<<gb, 256>>>(bufA, W1, bufH, n);
    k_agg<<<ab, 256>>>(bufH, b1, (float4*)bufA, n, 1);
    // layer 2
    k_gemm<<<gb, 256>>>(bufA, W2, bufH, n);
    k_agg<<<ab, 256>>>(bufH, b2, (float4*)bufA, n, 0);

    // pooling
    k_bounds<<<1, 128>>>(batch, n, ngraphs);
    k_pool<<<ngraphs, 128>>>(bufA, (float*)d_out);
}

// round 7
// speedup vs baseline: 1.6922x; 1.1614x over previous
#include <cuda_runtime.h>
#include <cuda_fp16.h>

#define ND        128
#define MAXN      50016
#define MAXE      1600000
#define MAXG      80
#define SCANB     1024
#define MAXBLK    64

// -------- device scratch (no allocation allowed) --------
__device__ float g_deg[MAXN];
__device__ float g_dinv[MAXN];
__device__ int   g_cnt[MAXN];
__device__ int   g_rowptr[MAXN + 1];
__device__ int   g_fill[MAXN];
__device__ int   g_bsum[MAXBLK];
__device__ int   g_boff[MAXBLK];
__device__ int   g_col[MAXE];
__device__ float g_val[MAXE];
__device__ float  g_bufA[50000 * ND];   // fp32: agg output / gemm input
__device__ __half g_bufH[50000 * ND];   // fp16: gemm output (messages)

__device__ __forceinline__ unsigned saddr(const void* p) {
    return (unsigned)__cvta_generic_to_shared(p);
}

// -------- degree init: self-loop weight 1 --------
__global__ void k_init(int n) {
    int i = blockIdx.x * blockDim.x + threadIdx.x;
    if (i < n) { g_deg[i] = 1.0f; g_cnt[i] = 0; }
}

// -------- degree + per-dst edge count --------
__global__ void k_deg(const int* __restrict__ dst, const float* __restrict__ ew, int E) {
    int e = blockIdx.x * blockDim.x + threadIdx.x;
    if (e < E) {
        int d = dst[e];
        atomicAdd(&g_deg[d], ew[e]);
        atomicAdd(&g_cnt[d], 1);
    }
}

// -------- scan phase A (block-local inclusive) + fused dinv --------
__global__ void k_scanA(int n) {
    __shared__ int warp_sums[32];
    int tid = threadIdx.x;
    int lane = tid & 31, wid = tid >> 5;
    int i = blockIdx.x * SCANB + tid;
    if (i < n) {
        float d = g_deg[i];
        g_dinv[i] = (d > 0.0f) ? rsqrtf(d) : 0.0f;
    }
    int x = (i < n) ? g_cnt[i] : 0;
    #pragma unroll
    for (int o = 1; o < 32; o <<= 1) {
        int y = __shfl_up_sync(0xFFFFFFFFu, x, o);
        if (lane >= o) x += y;
    }
    if (lane == 31) warp_sums[wid] = x;
    __syncthreads();
    if (wid == 0) {
        int w = warp_sums[lane];
        #pragma unroll
        for (int o = 1; o < 32; o <<= 1) {
            int y = __shfl_up_sync(0xFFFFFFFFu, w, o);
            if (lane >= o) w += y;
        }
        warp_sums[lane] = w;
    }
    __syncthreads();
    int incl = x + (wid > 0 ? warp_sums[wid - 1] : 0);
    if (i < n) g_rowptr[i + 1] = incl;
    if (tid == SCANB - 1) g_bsum[blockIdx.x] = incl;
}

// -------- phase B: exclusive scan of block sums (<=64) --------
__global__ void k_scanB(int nblk) {
    int tid = threadIdx.x;
    int v = (tid < nblk) ? g_bsum[tid] : 0;
    int x = v;
    #pragma unroll
    for (int o = 1; o < 32; o <<= 1) {
        int y = __shfl_up_sync(0xFFFFFFFFu, x, o);
        if ((tid & 31) >= o) x += y;
    }
    __shared__ int w0;
    if (tid == 31) w0 = x;
    __syncthreads();
    if (tid >= 32) x += w0;
    if (tid < nblk) g_boff[tid] = x - v;
}

// -------- phase C: add offsets + init g_fill --------
__global__ void k_scanC(int n) {
    int i = blockIdx.x * SCANB + threadIdx.x;
    if (i < n) {
        int r = g_rowptr[i + 1] + g_boff[blockIdx.x];
        g_rowptr[i + 1] = r;
        if (i + 1 < n) g_fill[i + 1] = r;
    }
    if (i == 0) { g_rowptr[0] = 0; g_fill[0] = 0; }
}

// -------- scatter edges into CSR (by dst), with precomputed norm --------
__global__ void k_csr(const int* __restrict__ src, const int* __restrict__ dst,
                      const float* __restrict__ ew, int E) {
    int e = blockIdx.x * blockDim.x + threadIdx.x;
    if (e < E) {
        int s = src[e], d = dst[e];
        int p = atomicAdd(&g_fill[d], 1);
        g_col[p] = s;
        g_val[p] = g_dinv[s] * ew[e] * g_dinv[d];
    }
}

// -------- fp16 tensor-core GEMM via ldmatrix + mma.m16n8k16 --------
// Block: 128 rows x 128 cols, 8 warps. K chunked by 64.
// Warp w: rows w*16..w*16+15, all 128 cols (16 n-tiles of 8).
__global__ void __launch_bounds__(256) k_gemm(const float* __restrict__ X,
                                              const float* __restrict__ W,
                                              __half* __restrict__ Y, int n) {
    __shared__ __align__(16) __half Xs[128][72];    // pitch 144B: ldsm conflict-free
    __shared__ __align__(16) __half Ws[64][136];    // pitch 272B: ldsm conflict-free
    const int tid  = threadIdx.x;
    const int warp = tid >> 5, lane = tid & 31;
    const int gid  = lane >> 2, tig = lane & 3;
    const int row0 = blockIdx.x * 128;
    const int wr   = warp * 16;

    float acc[16][4];
    #pragma unroll
    for (int t = 0; t < 16; t++)
        #pragma unroll
        for (int j = 0; j < 4; j++) acc[t][j] = 0.0f;

    for (int kc = 0; kc < ND; kc += 64) {
        // Ws chunk: k rows kc..kc+63, 128 cols, fp32 -> fp16
        #pragma unroll
        for (int i = 0; i < 8; i++) {
            int idx = tid + i * 256;            // 0..2047 float4s
            int k   = idx >> 5;                 // 0..63
            int c4  = (idx & 31) * 4;           // 0..124
            float4 v = *reinterpret_cast<const float4*>(W + (kc + k) * ND + c4);
            *reinterpret_cast<__half2*>(&Ws[k][c4])     = __floats2half2_rn(v.x, v.y);
            *reinterpret_cast<__half2*>(&Ws[k][c4 + 2]) = __floats2half2_rn(v.z, v.w);
        }
        // Xs chunk: 128 rows x 64 k, fp32 -> fp16
        #pragma unroll
        for (int i = 0; i < 8; i++) {
            int idx = tid + i * 256;
            int m   = idx >> 4;                 // 0..127
            int j4  = (idx & 15) * 4;           // 0..60
            float4 v = make_float4(0.f, 0.f, 0.f, 0.f);
            if (row0 + m < n)
                v = *reinterpret_cast<const float4*>(X + (row0 + m) * ND + kc + j4);
            *reinterpret_cast<__half2*>(&Xs[m][j4])     = __floats2half2_rn(v.x, v.y);
            *reinterpret_cast<__half2*>(&Xs[m][j4 + 2]) = __floats2half2_rn(v.z, v.w);
        }
        __syncthreads();
        #pragma unroll
        for (int ks = 0; ks < 4; ks++) {
            int k0 = ks * 16;
            unsigned a0, a1, a2, a3;
            unsigned aadr = saddr(&Xs[wr + (lane & 15)][k0 + (lane >> 4) * 8]);
            asm volatile("ldmatrix.sync.aligned.m8n8.x4.shared.b16 {%0,%1,%2,%3}, [%4];"
                         : "=r"(a0), "=r"(a1), "=r"(a2), "=r"(a3) : "r"(aadr));
            #pragma unroll
            for (int np = 0; np < 8; np++) {
                unsigned b0, b1, b2, b3;
                unsigned badr = saddr(&Ws[k0 + (lane & 15)][np * 16 + (lane >> 4) * 8]);
                asm volatile("ldmatrix.sync.aligned.m8n8.x4.trans.shared.b16 {%0,%1,%2,%3}, [%4];"
                             : "=r"(b0), "=r"(b1), "=r"(b2), "=r"(b3) : "r"(badr));
                asm volatile(
                    "mma.sync.aligned.m16n8k16.row.col.f32.f16.f16.f32 "
                    "{%0,%1,%2,%3},{%4,%5,%6,%7},{%8,%9},{%0,%1,%2,%3};"
                    : "+f"(acc[np * 2][0]), "+f"(acc[np * 2][1]),
                      "+f"(acc[np * 2][2]), "+f"(acc[np * 2][3])
                    : "r"(a0), "r"(a1), "r"(a2), "r"(a3), "r"(b0), "r"(b1));
                asm volatile(
                    "mma.sync.aligned.m16n8k16.row.col.f32.f16.f16.f32 "
                    "{%0,%1,%2,%3},{%4,%5,%6,%7},{%8,%9},{%0,%1,%2,%3};"
                    : "+f"(acc[np * 2 + 1][0]), "+f"(acc[np * 2 + 1][1]),
                      "+f"(acc[np * 2 + 1][2]), "+f"(acc[np * 2 + 1][3])
                    : "r"(a0), "r"(a1), "r"(a2), "r"(a3), "r"(b2), "r"(b3));
            }
        }
        __syncthreads();
    }
    int r0 = row0 + wr + gid;
    int r1 = r0 + 8;
    #pragma unroll
    for (int nt = 0; nt < 16; nt++) {
        int col = nt * 8 + tig * 2;
        if (r0 < n)
            *reinterpret_cast<__half2*>(Y + r0 * ND + col) =
                __floats2half2_rn(acc[nt][0], acc[nt][1]);
        if (r1 < n)
            *reinterpret_cast<__half2*>(Y + r1 * ND + col) =
                __floats2half2_rn(acc[nt][2], acc[nt][3]);
    }
}

__device__ __forceinline__ float4 h4_to_f4(uint2 u) {
    __half2 a = *reinterpret_cast<__half2*>(&u.x);
    __half2 b = *reinterpret_cast<__half2*>(&u.y);
    float2 fa = __half22float2(a);
    float2 fb = __half22float2(b);
    return make_float4(fa.x, fa.y, fb.x, fb.y);
}

// -------- CSR pull aggregation: warp per node, fp16 gather, fp32 accum --------
__global__ void __launch_bounds__(256) k_agg(const __half* __restrict__ XW,
                                             const float* __restrict__ bias,
                                             float4* __restrict__ OUT,
                                             int n, int relu) {
    int node = (blockIdx.x * blockDim.x + threadIdx.x) >> 5;
    int lane = threadIdx.x & 31;
    if (node >= n) return;

    const uint2* XWv = reinterpret_cast<const uint2*>(XW);

    float di = g_dinv[node];
    float sl = di * di;
    float4 a = h4_to_f4(XWv[node * 32 + lane]);
    float4 acc = make_float4(a.x * sl, a.y * sl, a.z * sl, a.w * sl);

    int e0 = g_rowptr[node], e1 = g_rowptr[node + 1];
    int e = e0;
    for (; e + 4 <= e1; e += 4) {
        int   c0 = g_col[e],     c1 = g_col[e + 1];
        int   c2 = g_col[e + 2], c3 = g_col[e + 3];
        float v0 = g_val[e],     v1 = g_val[e + 1];
        float v2 = g_val[e + 2], v3 = g_val[e + 3];
        uint2 u0 = XWv[c0 * 32 + lane];
        uint2 u1 = XWv[c1 * 32 + lane];
        uint2 u2 = XWv[c2 * 32 + lane];
        uint2 u3 = XWv[c3 * 32 + lane];
        float4 m0 = h4_to_f4(u0);
        float4 m1 = h4_to_f4(u1);
        float4 m2 = h4_to_f4(u2);
        float4 m3 = h4_to_f4(u3);
        acc.x = fmaf(v0, m0.x, acc.x); acc.y = fmaf(v0, m0.y, acc.y);
        acc.z = fmaf(v0, m0.z, acc.z); acc.w = fmaf(v0, m0.w, acc.w);
        acc.x = fmaf(v1, m1.x, acc.x); acc.y = fmaf(v1, m1.y, acc.y);
        acc.z = fmaf(v1, m1.z, acc.z); acc.w = fmaf(v1, m1.w, acc.w);
        acc.x = fmaf(v2, m2.x, acc.x); acc.y = fmaf(v2, m2.y, acc.y);
        acc.z = fmaf(v2, m2.z, acc.z); acc.w = fmaf(v2, m2.w, acc.w);
        acc.x = fmaf(v3, m3.x, acc.x); acc.y = fmaf(v3, m3.y, acc.y);
        acc.z = fmaf(v3, m3.z, acc.z); acc.w = fmaf(v3, m3.w, acc.w);
    }
    for (; e < e1; e++) {
        int c = g_col[e];
        float v = g_val[e];
        float4 m = h4_to_f4(XWv[c * 32 + lane]);
        acc.x = fmaf(v, m.x, acc.x); acc.y = fmaf(v, m.y, acc.y);
        acc.z = fmaf(v, m.z, acc.z); acc.w = fmaf(v, m.w, acc.w);
    }
    float4 b = reinterpret_cast<const float4*>(bias)[lane];
    acc.x += b.x; acc.y += b.y; acc.z += b.z; acc.w += b.w;
    if (relu) {
        acc.x = fmaxf(acc.x, 0.f); acc.y = fmaxf(acc.y, 0.f);
        acc.z = fmaxf(acc.z, 0.f); acc.w = fmaxf(acc.w, 0.f);
    }
    OUT[node * 32 + lane] = acc;
}

// -------- global mean pool: one block (1024 thr) per graph, fused bounds ----
__global__ void __launch_bounds__(1024) k_pool(const float4* __restrict__ h,
                                               const int* __restrict__ batch,
                                               int n, float4* __restrict__ out) {
    __shared__ float4 part[32][32];
    __shared__ int sse[2];
    int g = blockIdx.x;
    if (threadIdx.x < 2) {
        int target = g + threadIdx.x;
        int lo = 0, hi = n;
        while (lo < hi) {
            int mid = (lo + hi) >> 1;
            if (batch[mid] < target) lo = mid + 1; else hi = mid;
        }
        sse[threadIdx.x] = lo;
    }
    __syncthreads();
    int s = sse[0], e = sse[1];
    int rg = threadIdx.x >> 5;     // 0..31 row-group
    int ch = threadIdx.x & 31;     // float4 dim-chunk
    float4 acc = make_float4(0.f, 0.f, 0.f, 0.f);
    for (int i = s + rg; i < e; i += 32) {
        float4 v = h[i * 32 + ch];
        acc.x += v.x; acc.y += v.y; acc.z += v.z; acc.w += v.w;
    }
    part[rg][ch] = acc;
    __syncthreads();
    #pragma unroll
    for (int off = 16; off > 0; off >>= 1) {
        if (rg < off) {
            float4 o = part[rg + off][ch];
            float4 m = part[rg][ch];
            m.x += o.x; m.y += o.y; m.z += o.z; m.w += o.w;
            part[rg][ch] = m;
        }
        __syncthreads();
    }
    if (rg == 0) {
        float inv = 1.0f / (float)((e - s) > 0 ? (e - s) : 1);
        float4 m = part[0][ch];
        m.x *= inv; m.y *= inv; m.z *= inv; m.w *= inv;
        out[g * 32 + ch] = m;
    }
}

extern "C" void kernel_launch(void* const* d_in, const int* in_sizes, int n_in,
                              void* d_out, int out_size) {
    const float* x     = (const float*)d_in[0];
    const int*   ei    = (const int*)d_in[1];
    const float* ew    = (const float*)d_in[2];
    const int*   batch = (const int*)d_in[3];
    const float* W0    = (const float*)d_in[4];
    const float* b0    = (const float*)d_in[5];
    const float* W1    = (const float*)d_in[6];
    const float* b1    = (const float*)d_in[7];
    const float* W2    = (const float*)d_in[8];
    const float* b2    = (const float*)d_in[9];

    int n = in_sizes[0] / ND;
    int E = in_sizes[1] / 2;
    int ngraphs = out_size / ND;
    const int* src = ei;
    const int* dst = ei + E;

    float  *bufA;
    __half *bufH;
    cudaGetSymbolAddress((void**)&bufA, g_bufA);
    cudaGetSymbolAddress((void**)&bufH, g_bufH);

    int nb  = (n + 255) / 256;
    int eb  = (E + 255) / 256;
    int gb  = (n + 127) / 128;
    int ab  = (int)(((long long)n * 32 + 255) / 256);
    int sbk = (n + SCANB - 1) / SCANB;

    // normalization + CSR build
    k_init<<<nb, 256>>>(n);
    k_deg<<<eb, 256>>>(dst, ew, E);
    k_scanA<<<sbk, SCANB>>>(n);
    k_scanB<<<1, 64>>>(sbk);
    k_scanC<<<sbk, SCANB>>>(n);
    k_csr<<<eb, 256>>>(src, dst, ew, E);

    // layer 0
    k_gemm<<<gb, 256>>>(x, W0, bufH, n);
    k_agg<<<ab, 256>>>(bufH, b0, (float4*)bufA, n, 1);
    // layer 1
    k_gemm<<<gb, 256>>>(bufA, W1, bufH, n);
    k_agg<<<ab, 256>>>(bufH, b1, (float4*)bufA, n, 1);
    // layer 2
    k_gemm<<<gb, 256>>>(bufA, W2, bufH, n);
    k_agg<<<ab, 256>>>(bufH, b2, (float4*)bufA, n, 0);

    // pooling (bounds fused)
    k_pool<<<ngraphs, 1024>>>((const float4*)bufA, batch, n, (float4*)d_out);
}

// round 8
// speedup vs baseline: 1.7687x; 1.0452x over previous
#include <cuda_runtime.h>
#include <cuda_fp16.h>

#define ND        128
#define MAXN      50016
#define MAXE      1600000
#define SCANB     1024
#define MAXBLK    64

// -------- device scratch (no allocation allowed) --------
// g_deg/g_cnt obey a zero-restore protocol: zero at module load, k_deg
// accumulates, k_scanA consumes AND re-zeroes them, so every graph replay
// sees the same initial state. (Self-loop +1 folded into k_scanA.)
__device__ float g_deg[MAXN];
__device__ float g_dinv[MAXN];
__device__ int   g_cnt[MAXN];
__device__ int   g_rowptr[MAXN + 1];
__device__ int   g_fill[MAXN];
__device__ int   g_bsum[MAXBLK];
__device__ int   g_col[MAXE];
__device__ float g_val[MAXE];
__device__ __align__(256) float  g_bufA [50000 * ND];  // fp32: final agg out
__device__ __align__(256) __half g_bufH [50000 * ND];  // fp16: gemm out (messages)
__device__ __align__(256) __half g_bufH2[50000 * ND];  // fp16: interior agg out

__device__ __forceinline__ unsigned saddr(const void* p) {
    return (unsigned)__cvta_generic_to_shared(p);
}

// -------- degree + per-dst edge count (buffers pre-zeroed by protocol) ------
__global__ void k_deg(const int* __restrict__ dst, const float* __restrict__ ew, int E) {
    int e = blockIdx.x * blockDim.x + threadIdx.x;
    if (e < E) {
        int d = dst[e];
        atomicAdd(&g_deg[d], ew[e]);
        atomicAdd(&g_cnt[d], 1);
    }
}

// -------- scan phase A: block-local inclusive scan + dinv + zero-restore ----
__global__ void k_scanA(int n) {
    __shared__ int warp_sums[32];
    int tid = threadIdx.x;
    int lane = tid & 31, wid = tid >> 5;
    int i = blockIdx.x * SCANB + tid;
    int x = 0;
    if (i < n) {
        float d = g_deg[i] + 1.0f;       // implicit self-loop (weight 1); d >= 1
        g_dinv[i] = rsqrtf(d);
        g_deg[i] = 0.0f;                 // restore protocol invariant
        x = g_cnt[i];
        g_cnt[i] = 0;                    // restore protocol invariant
    }
    #pragma unroll
    for (int o = 1; o < 32; o <<= 1) {
        int y = __shfl_up_sync(0xFFFFFFFFu, x, o);
        if (lane >= o) x += y;
    }
    if (lane == 31) warp_sums[wid] = x;
    __syncthreads();
    if (wid == 0) {
        int w = warp_sums[lane];
        #pragma unroll
        for (int o = 1; o < 32; o <<= 1) {
            int y = __shfl_up_sync(0xFFFFFFFFu, w, o);
            if (lane >= o) w += y;
        }
        warp_sums[lane] = w;
    }
    __syncthreads();
    int incl = x + (wid > 0 ? warp_sums[wid - 1] : 0);
    if (i < n) g_rowptr[i + 1] = incl;
    if (tid == SCANB - 1) g_bsum[blockIdx.x] = incl;
}

// -------- phase C: per-block offset via local reduce of block sums ---------
__global__ void k_scanC(int n) {
    __shared__ int s_off;
    if (threadIdx.x < 32) {
        int acc = 0;
        for (int base = 0; base < (int)blockIdx.x; base += 32) {
            int idx = base + (int)threadIdx.x;
            int v = (idx < (int)blockIdx.x) ? g_bsum[idx] : 0;
            #pragma unroll
            for (int o = 16; o > 0; o >>= 1)
                v += __shfl_xor_sync(0xFFFFFFFFu, v, o);
            acc += v;
        }
        if (threadIdx.x == 0) s_off = acc;
    }
    __syncthreads();
    int off = s_off;
    int i = blockIdx.x * SCANB + threadIdx.x;
    if (i < n) {
        int r = g_rowptr[i + 1] + off;
        g_rowptr[i + 1] = r;
        if (i + 1 < n) g_fill[i + 1] = r;
    }
    if (i == 0) { g_rowptr[0] = 0; g_fill[0] = 0; }
}

// -------- scatter edges into CSR (by dst), with precomputed norm --------
__global__ void k_csr(const int* __restrict__ src, const int* __restrict__ dst,
                      const float* __restrict__ ew, int E) {
    int e = blockIdx.x * blockDim.x + threadIdx.x;
    if (e < E) {
        int s = src[e], d = dst[e];
        int p = atomicAdd(&g_fill[d], 1);
        g_col[p] = s;
        g_val[p] = g_dinv[s] * ew[e] * g_dinv[d];
    }
}

// -------- fp16 tensor-core GEMM via ldmatrix + mma.m16n8k16 --------
// Block: 128 rows x 128 cols, 8 warps. K chunked by 64.
template<bool HALF_IN>
__global__ void __launch_bounds__(256) k_gemm(const void* __restrict__ Xv,
                                              const float* __restrict__ W,
                                              __half* __restrict__ Y, int n) {
    __shared__ __align__(16) __half Xs[128][72];    // pitch 144B
    __shared__ __align__(16) __half Ws[64][136];    // pitch 272B
    const int tid  = threadIdx.x;
    const int warp = tid >> 5, lane = tid & 31;
    const int gid  = lane >> 2, tig = lane & 3;
    const int row0 = blockIdx.x * 128;
    const int wr   = warp * 16;

    float acc[16][4];
    #pragma unroll
    for (int t = 0; t < 16; t++)
        #pragma unroll
        for (int j = 0; j < 4; j++) acc[t][j] = 0.0f;

    for (int kc = 0; kc < ND; kc += 64) {
        #pragma unroll
        for (int i = 0; i < 8; i++) {
            int idx = tid + i * 256;
            int k   = idx >> 5;
            int c4  = (idx & 31) * 4;
            float4 v = *reinterpret_cast<const float4*>(W + (kc + k) * ND + c4);
            *reinterpret_cast<__half2*>(&Ws[k][c4])     = __floats2half2_rn(v.x, v.y);
            *reinterpret_cast<__half2*>(&Ws[k][c4 + 2]) = __floats2half2_rn(v.z, v.w);
        }
        if (HALF_IN) {
            const __half* X = (const __half*)Xv;
            #pragma unroll
            for (int i = 0; i < 4; i++) {
                int idx = tid + i * 256;          // 0..1023 uint4s (8 halves)
                int m   = idx >> 3;               // 0..127
                int j8  = (idx & 7) * 8;          // 0..56
                uint4 v = make_uint4(0, 0, 0, 0);
                if (row0 + m < n)
                    v = *reinterpret_cast<const uint4*>(X + (row0 + m) * ND + kc + j8);
                *reinterpret_cast<uint4*>(&Xs[m][j8]) = v;
            }
        } else {
            const float* X = (const float*)Xv;
            #pragma unroll
            for (int i = 0; i < 8; i++) {
                int idx = tid + i * 256;
                int m   = idx >> 4;
                int j4  = (idx & 15) * 4;
                float4 v = make_float4(0.f, 0.f, 0.f, 0.f);
                if (row0 + m < n)
                    v = *reinterpret_cast<const float4*>(X + (row0 + m) * ND + kc + j4);
                *reinterpret_cast<__half2*>(&Xs[m][j4])     = __floats2half2_rn(v.x, v.y);
                *reinterpret_cast<__half2*>(&Xs[m][j4 + 2]) = __floats2half2_rn(v.z, v.w);
            }
        }
        __syncthreads();
        #pragma unroll
        for (int ks = 0; ks < 4; ks++) {
            int k0 = ks * 16;
            unsigned a0, a1, a2, a3;
            unsigned aadr = saddr(&Xs[wr + (lane & 15)][k0 + (lane >> 4) * 8]);
            asm volatile("ldmatrix.sync.aligned.m8n8.x4.shared.b16 {%0,%1,%2,%3}, [%4];"
                         : "=r"(a0), "=r"(a1), "=r"(a2), "=r"(a3) : "r"(aadr));
            #pragma unroll
            for (int np = 0; np < 8; np++) {
                unsigned b0, b1, b2, b3;
                unsigned badr = saddr(&Ws[k0 + (lane & 15)][np * 16 + (lane >> 4) * 8]);
                asm volatile("ldmatrix.sync.aligned.m8n8.x4.trans.shared.b16 {%0,%1,%2,%3}, [%4];"
                             : "=r"(b0), "=r"(b1), "=r"(b2), "=r"(b3) : "r"(badr));
                asm volatile(
                    "mma.sync.aligned.m16n8k16.row.col.f32.f16.f16.f32 "
                    "{%0,%1,%2,%3},{%4,%5,%6,%7},{%8,%9},{%0,%1,%2,%3};"
                    : "+f"(acc[np * 2][0]), "+f"(acc[np * 2][1]),
                      "+f"(acc[np * 2][2]), "+f"(acc[np * 2][3])
                    : "r"(a0), "r"(a1), "r"(a2), "r"(a3), "r"(b0), "r"(b1));
                asm volatile(
                    "mma.sync.aligned.m16n8k16.row.col.f32.f16.f16.f32 "
                    "{%0,%1,%2,%3},{%4,%5,%6,%7},{%8,%9},{%0,%1,%2,%3};"
                    : "+f"(acc[np * 2 + 1][0]), "+f"(acc[np * 2 + 1][1]),
                      "+f"(acc[np * 2 + 1][2]), "+f"(acc[np * 2 + 1][3])
                    : "r"(a0), "r"(a1), "r"(a2), "r"(a3), "r"(b2), "r"(b3));
            }
        }
        __syncthreads();
    }
    int r0 = row0 + wr + gid;
    int r1 = r0 + 8;
    #pragma unroll
    for (int nt = 0; nt < 16; nt++) {
        int col = nt * 8 + tig * 2;
        if (r0 < n)
            *reinterpret_cast<__half2*>(Y + r0 * ND + col) =
                __floats2half2_rn(acc[nt][0], acc[nt][1]);
        if (r1 < n)
            *reinterpret_cast<__half2*>(Y + r1 * ND + col) =
                __floats2half2_rn(acc[nt][2], acc[nt][3]);
    }
}

__device__ __forceinline__ float4 h4_to_f4(uint2 u) {
    __half2 a = *reinterpret_cast<__half2*>(&u.x);
    __half2 b = *reinterpret_cast<__half2*>(&u.y);
    float2 fa = __half22float2(a);
    float2 fb = __half22float2(b);
    return make_float4(fa.x, fa.y, fb.x, fb.y);
}

// -------- CSR pull aggregation: warp/node, fp16 gather, fp32 accum, 8-wide --
template<bool HALF_OUT>
__global__ void __launch_bounds__(256) k_agg(const __half* __restrict__ XW,
                                             const float* __restrict__ bias,
                                             void* __restrict__ OUTv,
                                             int n, int relu) {
    int node = (blockIdx.x * blockDim.x + threadIdx.x) >> 5;
    int lane = threadIdx.x & 31;
    if (node >= n) return;

    const uint2* XWv = reinterpret_cast<const uint2*>(XW);

    float di = g_dinv[node];
    float sl = di * di;
    float4 a = h4_to_f4(XWv[node * 32 + lane]);
    float4 acc = make_float4(a.x * sl, a.y * sl, a.z * sl, a.w * sl);

    int e0 = g_rowptr[node], e1 = g_rowptr[node + 1];
    int e = e0;
    for (; e + 8 <= e1; e += 8) {
        int   c[8]; float v[8]; uint2 u[8];
        #pragma unroll
        for (int j = 0; j < 8; j++) { c[j] = g_col[e + j]; v[j] = g_val[e + j]; }
        #pragma unroll
        for (int j = 0; j < 8; j++) u[j] = XWv[c[j] * 32 + lane];
        #pragma unroll
        for (int j = 0; j < 8; j++) {
            float4 m = h4_to_f4(u[j]);
            acc.x = fmaf(v[j], m.x, acc.x); acc.y = fmaf(v[j], m.y, acc.y);
            acc.z = fmaf(v[j], m.z, acc.z); acc.w = fmaf(v[j], m.w, acc.w);
        }
    }
    if (e + 4 <= e1) {
        int   c[4]; float v[4]; uint2 u[4];
        #pragma unroll
        for (int j = 0; j < 4; j++) { c[j] = g_col[e + j]; v[j] = g_val[e + j]; }
        #pragma unroll
        for (int j = 0; j < 4; j++) u[j] = XWv[c[j] * 32 + lane];
        #pragma unroll
        for (int j = 0; j < 4; j++) {
            float4 m = h4_to_f4(u[j]);
            acc.x = fmaf(v[j], m.x, acc.x); acc.y = fmaf(v[j], m.y, acc.y);
            acc.z = fmaf(v[j], m.z, acc.z); acc.w = fmaf(v[j], m.w, acc.w);
        }
        e += 4;
    }
    for (; e < e1; e++) {
        int cc = g_col[e];
        float vv = g_val[e];
        float4 m = h4_to_f4(XWv[cc * 32 + lane]);
        acc.x = fmaf(vv, m.x, acc.x); acc.y = fmaf(vv, m.y, acc.y);
        acc.z = fmaf(vv, m.z, acc.z); acc.w = fmaf(vv, m.w, acc.w);
    }
    float4 b = reinterpret_cast<const float4*>(bias)[lane];
    acc.x += b.x; acc.y += b.y; acc.z += b.z; acc.w += b.w;
    if (relu) {
        acc.x = fmaxf(acc.x, 0.f); acc.y = fmaxf(acc.y, 0.f);
        acc.z = fmaxf(acc.z, 0.f); acc.w = fmaxf(acc.w, 0.f);
    }
    if (HALF_OUT) {
        uint2 o;
        __half2 h0 = __floats2half2_rn(acc.x, acc.y);
        __half2 h1 = __floats2half2_rn(acc.z, acc.w);
        o.x = *reinterpret_cast<unsigned*>(&h0);
        o.y = *reinterpret_cast<unsigned*>(&h1);
        reinterpret_cast<uint2*>(OUTv)[node * 32 + lane] = o;
    } else {
        reinterpret_cast<float4*>(OUTv)[node * 32 + lane] = acc;
    }
}

// -------- global mean pool: one block (1024 thr) per graph, fused bounds ----
__global__ void __launch_bounds__(1024) k_pool(const float4* __restrict__ h,
                                               const int* __restrict__ batch,
                                               int n, float4* __restrict__ out) {
    __shared__ float4 part[32][32];
    __shared__ int sse[2];
    int g = blockIdx.x;
    if (threadIdx.x < 2) {
        int target = g + threadIdx.x;
        int lo = 0, hi = n;
        while (lo < hi) {
            int mid = (lo + hi) >> 1;
            if (batch[mid] < target) lo = mid + 1; else hi = mid;
        }
        sse[threadIdx.x] = lo;
    }
    __syncthreads();
    int s = sse[0], e = sse[1];
    int rg = threadIdx.x >> 5;
    int ch = threadIdx.x & 31;
    float4 acc = make_float4(0.f, 0.f, 0.f, 0.f);
    for (int i = s + rg; i < e; i += 32) {
        float4 v = h[i * 32 + ch];
        acc.x += v.x; acc.y += v.y; acc.z += v.z; acc.w += v.w;
    }
    part[rg][ch] = acc;
    __syncthreads();
    #pragma unroll
    for (int off = 16; off > 0; off >>= 1) {
        if (rg < off) {
            float4 o = part[rg + off][ch];
            float4 m = part[rg][ch];
            m.x += o.x; m.y += o.y; m.z += o.z; m.w += o.w;
            part[rg][ch] = m;
        }
        __syncthreads();
    }
    if (rg == 0) {
        float inv = 1.0f / (float)((e - s) > 0 ? (e - s) : 1);
        float4 m = part[0][ch];
        m.x *= inv; m.y *= inv; m.z *= inv; m.w *= inv;
        out[g * 32 + ch] = m;
    }
}

extern "C" void kernel_launch(void* const* d_in, const int* in_sizes, int n_in,
                              void* d_out, int out_size) {
    const float* x     = (const float*)d_in[0];
    const int*   ei    = (const int*)d_in[1];
    const float* ew    = (const float*)d_in[2];
    const int*   batch = (const int*)d_in[3];
    const float* W0    = (const float*)d_in[4];
    const float* b0    = (const float*)d_in[5];
    const float* W1    = (const float*)d_in[6];
    const float* b1    = (const float*)d_in[7];
    const float* W2    = (const float*)d_in[8];
    const float* b2    = (const float*)d_in[9];

    int n = in_sizes[0] / ND;
    int E = in_sizes[1] / 2;
    int ngraphs = out_size / ND;
    const int* src = ei;
    const int* dst = ei + E;

    float  *bufA;
    __half *bufH, *bufH2;
    cudaGetSymbolAddress((void**)&bufA,  g_bufA);
    cudaGetSymbolAddress((void**)&bufH,  g_bufH);
    cudaGetSymbolAddress((void**)&bufH2, g_bufH2);

    int eb  = (E + 255) / 256;
    int gb  = (n + 127) / 128;
    int ab  = (int)(((long long)n * 32 + 255) / 256);
    int sbk = (n + SCANB - 1) / SCANB;

    // normalization + CSR build (g_deg/g_cnt zeroed by protocol)
    k_deg<<<eb, 256>>>(dst, ew, E);
    k_scanA<<<sbk, SCANB>>>(n);
    k_scanC<<<sbk, SCANB>>>(n);
    k_csr<<<eb, 256>>>(src, dst, ew, E);

    // layer 0 (fp32 in -> fp16 interior)
    k_gemm<false><<<gb, 256>>>(x, W0, bufH, n);
    k_agg<true><<<ab, 256>>>(bufH, b0, bufH2, n, 1);
    // layer 1 (fp16 in/out)
    k_gemm<true><<<gb, 256>>>(bufH2, W1, bufH, n);
    k_agg<true><<<ab, 256>>>(bufH, b1, bufH2, n, 1);
    // layer 2 (fp16 in -> fp32 out for pooling)
    k_gemm<true><<<gb, 256>>>(bufH2, W2, bufH, n);
    k_agg<false><<<ab, 256>>>(bufH, b2, bufA, n, 0);

    // pooling (bounds fused)
    k_pool<<<ngraphs, 1024>>>((const float4*)bufA, batch, n, (float4*)d_out);
}

// round 9
// speedup vs baseline: 1.8720x; 1.0584x over previous
#include <cuda_runtime.h>
#include <cuda_fp16.h>

#define ND        128
#define MAXN      50016
#define MAXE      1600000
#define SCANB     1024
#define MAXBLK    64

// -------- device scratch (no allocation allowed) --------
// g_deg/g_cnt obey a zero-restore protocol: zero at module load, k_deg
// accumulates, k_scanA consumes AND re-zeroes them, so every graph replay
// sees the same initial state. (Self-loop +1 folded into k_scanA.)
__device__ float g_deg[MAXN];
__device__ float g_dinv[MAXN];
__device__ int   g_cnt[MAXN];
__device__ int   g_rowptr[MAXN + 1];
__device__ int   g_bsum[MAXBLK];
__device__ int   g_rank[MAXE];          // per-edge rank within its dst segment
__device__ uint2 g_csr[MAXE];           // packed {src, val_bits}, val = ew*dinv[src]
__device__ __align__(256) float  g_bufA [50000 * ND];  // fp32: final agg out
__device__ __align__(256) __half g_bufH [50000 * ND];  // fp16: gemm out (messages)
__device__ __align__(256) __half g_bufH2[50000 * ND];  // fp16: interior agg out

__device__ __forceinline__ unsigned saddr(const void* p) {
    return (unsigned)__cvta_generic_to_shared(p);
}

// -------- degree + per-dst edge count + rank (buffers pre-zeroed) ------
__global__ void k_deg(const int* __restrict__ dst, const float* __restrict__ ew, int E) {
    int e = blockIdx.x * blockDim.x + threadIdx.x;
    if (e < E) {
        int d = dst[e];
        atomicAdd(&g_deg[d], ew[e]);
        g_rank[e] = atomicAdd(&g_cnt[d], 1);   // rank doubles as the CSR slot
    }
}

// -------- scan phase A: block-local inclusive scan + dinv + zero-restore ----
__global__ void k_scanA(int n) {
    __shared__ int warp_sums[32];
    int tid = threadIdx.x;
    int lane = tid & 31, wid = tid >> 5;
    int i = blockIdx.x * SCANB + tid;
    int x = 0;
    if (i < n) {
        float d = g_deg[i] + 1.0f;       // implicit self-loop (weight 1); d >= 1
        g_dinv[i] = rsqrtf(d);
        g_deg[i] = 0.0f;                 // restore protocol invariant
        x = g_cnt[i];
        g_cnt[i] = 0;                    // restore protocol invariant
    }
    #pragma unroll
    for (int o = 1; o < 32; o <<= 1) {
        int y = __shfl_up_sync(0xFFFFFFFFu, x, o);
        if (lane >= o) x += y;
    }
    if (lane == 31) warp_sums[wid] = x;
    __syncthreads();
    if (wid == 0) {
        int w = warp_sums[lane];
        #pragma unroll
        for (int o = 1; o < 32; o <<= 1) {
            int y = __shfl_up_sync(0xFFFFFFFFu, w, o);
            if (lane >= o) w += y;
        }
        warp_sums[lane] = w;
    }
    __syncthreads();
    int incl = x + (wid > 0 ? warp_sums[wid - 1] : 0);
    if (i < n) g_rowptr[i + 1] = incl;
    if (tid == SCANB - 1) g_bsum[blockIdx.x] = incl;
}

// -------- phase C: per-block offset via local reduce of block sums ---------
__global__ void k_scanC(int n) {
    __shared__ int s_off;
    if (threadIdx.x < 32) {
        int acc = 0;
        for (int base = 0; base < (int)blockIdx.x; base += 32) {
            int idx = base + (int)threadIdx.x;
            int v = (idx < (int)blockIdx.x) ? g_bsum[idx] : 0;
            #pragma unroll
            for (int o = 16; o > 0; o >>= 1)
                v += __shfl_xor_sync(0xFFFFFFFFu, v, o);
            acc += v;
        }
        if (threadIdx.x == 0) s_off = acc;
    }
    __syncthreads();
    int off = s_off;
    int i = blockIdx.x * SCANB + threadIdx.x;
    if (i < n) g_rowptr[i + 1] += off;
    if (i == 0) g_rowptr[0] = 0;
}

// -------- scatter edges into CSR (by dst): NO atomics, packed 8B store -----
// val stores ew * dinv[src]; dinv[dst] factored out into k_agg.
__global__ void k_csr(const int* __restrict__ src, const int* __restrict__ dst,
                      const float* __restrict__ ew, int E) {
    int e = blockIdx.x * blockDim.x + threadIdx.x;
    if (e < E) {
        int s = src[e], d = dst[e];
        int p = g_rowptr[d] + g_rank[e];
        uint2 u;
        u.x = (unsigned)s;
        float v = g_dinv[s] * ew[e];
        u.y = __float_as_uint(v);
        g_csr[p] = u;
    }
}

// -------- fp16 tensor-core GEMM via ldmatrix + mma.m16n8k16 --------
// Block: 128 rows x 128 cols, 8 warps. K chunked by 64.
template<bool HALF_IN>
__global__ void __launch_bounds__(256) k_gemm(const void* __restrict__ Xv,
                                              const float* __restrict__ W,
                                              __half* __restrict__ Y, int n) {
    __shared__ __align__(16) __half Xs[128][72];    // pitch 144B
    __shared__ __align__(16) __half Ws[64][136];    // pitch 272B
    const int tid  = threadIdx.x;
    const int warp = tid >> 5, lane = tid & 31;
    const int gid  = lane >> 2, tig = lane & 3;
    const int row0 = blockIdx.x * 128;
    const int wr   = warp * 16;

    float acc[16][4];
    #pragma unroll
    for (int t = 0; t < 16; t++)
        #pragma unroll
        for (int j = 0; j < 4; j++) acc[t][j] = 0.0f;

    for (int kc = 0; kc < ND; kc += 64) {
        #pragma unroll
        for (int i = 0; i < 8; i++) {
            int idx = tid + i * 256;
            int k   = idx >> 5;
            int c4  = (idx & 31) * 4;
            float4 v = *reinterpret_cast<const float4*>(W + (kc + k) * ND + c4);
            *reinterpret_cast<__half2*>(&Ws[k][c4])     = __floats2half2_rn(v.x, v.y);
            *reinterpret_cast<__half2*>(&Ws[k][c4 + 2]) = __floats2half2_rn(v.z, v.w);
        }
        if (HALF_IN) {
            const __half* X = (const __half*)Xv;
            #pragma unroll
            for (int i = 0; i < 4; i++) {
                int idx = tid + i * 256;
                int m   = idx >> 3;
                int j8  = (idx & 7) * 8;
                uint4 v = make_uint4(0, 0, 0, 0);
                if (row0 + m < n)
                    v = *reinterpret_cast<const uint4*>(X + (row0 + m) * ND + kc + j8);
                *reinterpret_cast<uint4*>(&Xs[m][j8]) = v;
            }
        } else {
            const float* X = (const float*)Xv;
            #pragma unroll
            for (int i = 0; i < 8; i++) {
                int idx = tid + i * 256;
                int m   = idx >> 4;
                int j4  = (idx & 15) * 4;
                float4 v = make_float4(0.f, 0.f, 0.f, 0.f);
                if (row0 + m < n)
                    v = *reinterpret_cast<const float4*>(X + (row0 + m) * ND + kc + j4);
                *reinterpret_cast<__half2*>(&Xs[m][j4])     = __floats2half2_rn(v.x, v.y);
                *reinterpret_cast<__half2*>(&Xs[m][j4 + 2]) = __floats2half2_rn(v.z, v.w);
            }
        }
        __syncthreads();
        #pragma unroll
        for (int ks = 0; ks < 4; ks++) {
            int k0 = ks * 16;
            unsigned a0, a1, a2, a3;
            unsigned aadr = saddr(&Xs[wr + (lane & 15)][k0 + (lane >> 4) * 8]);
            asm volatile("ldmatrix.sync.aligned.m8n8.x4.shared.b16 {%0,%1,%2,%3}, [%4];"
                         : "=r"(a0), "=r"(a1), "=r"(a2), "=r"(a3) : "r"(aadr));
            #pragma unroll
            for (int np = 0; np < 8; np++) {
                unsigned b0, b1, b2, b3;
                unsigned badr = saddr(&Ws[k0 + (lane & 15)][np * 16 + (lane >> 4) * 8]);
                asm volatile("ldmatrix.sync.aligned.m8n8.x4.trans.shared.b16 {%0,%1,%2,%3}, [%4];"
                             : "=r"(b0), "=r"(b1), "=r"(b2), "=r"(b3) : "r"(badr));
                asm volatile(
                    "mma.sync.aligned.m16n8k16.row.col.f32.f16.f16.f32 "
                    "{%0,%1,%2,%3},{%4,%5,%6,%7},{%8,%9},{%0,%1,%2,%3};"
                    : "+f"(acc[np * 2][0]), "+f"(acc[np * 2][1]),
                      "+f"(acc[np * 2][2]), "+f"(acc[np * 2][3])
                    : "r"(a0), "r"(a1), "r"(a2), "r"(a3), "r"(b0), "r"(b1));
                asm volatile(
                    "mma.sync.aligned.m16n8k16.row.col.f32.f16.f16.f32 "
                    "{%0,%1,%2,%3},{%4,%5,%6,%7},{%8,%9},{%0,%1,%2,%3};"
                    : "+f"(acc[np * 2 + 1][0]), "+f"(acc[np * 2 + 1][1]),
                      "+f"(acc[np * 2 + 1][2]), "+f"(acc[np * 2 + 1][3])
                    : "r"(a0), "r"(a1), "r"(a2), "r"(a3), "r"(b2), "r"(b3));
            }
        }
        __syncthreads();
    }
    int r0 = row0 + wr + gid;
    int r1 = r0 + 8;
    #pragma unroll
    for (int nt = 0; nt < 16; nt++) {
        int col = nt * 8 + tig * 2;
        if (r0 < n)
            *reinterpret_cast<__half2*>(Y + r0 * ND + col) =
                __floats2half2_rn(acc[nt][0], acc[nt][1]);
        if (r1 < n)
            *reinterpret_cast<__half2*>(Y + r1 * ND + col) =
                __floats2half2_rn(acc[nt][2], acc[nt][3]);
    }
}

__device__ __forceinline__ float4 h4_to_f4(uint2 u) {
    __half2 a = *reinterpret_cast<__half2*>(&u.x);
    __half2 b = *reinterpret_cast<__half2*>(&u.y);
    float2 fa = __half22float2(a);
    float2 fb = __half22float2(b);
    return make_float4(fa.x, fa.y, fb.x, fb.y);
}

// -------- CSR pull aggregation: warp/node, fp16 gather, fp32 accum ---------
// out = di * ( self*di + sum_j val_j * msg_j ) + bias,  val_j = ew*dinv[src]
template<bool HALF_OUT>
__global__ void __launch_bounds__(256) k_agg(const __half* __restrict__ XW,
                                             const float* __restrict__ bias,
                                             void* __restrict__ OUTv,
                                             int n, int relu) {
    int node = (blockIdx.x * blockDim.x + threadIdx.x) >> 5;
    int lane = threadIdx.x & 31;
    if (node >= n) return;

    const uint2* XWv = reinterpret_cast<const uint2*>(XW);

    float di = g_dinv[node];
    float4 a = h4_to_f4(XWv[node * 32 + lane]);
    float4 acc = make_float4(a.x * di, a.y * di, a.z * di, a.w * di);

    int e0 = g_rowptr[node], e1 = g_rowptr[node + 1];
    int e = e0;
    for (; e + 8 <= e1; e += 8) {
        uint2 cv[8]; uint2 u[8];
        #pragma unroll
        for (int j = 0; j < 8; j++) cv[j] = g_csr[e + j];
        #pragma unroll
        for (int j = 0; j < 8; j++) u[j] = XWv[cv[j].x * 32 + lane];
        #pragma unroll
        for (int j = 0; j < 8; j++) {
            float v = __uint_as_float(cv[j].y);
            float4 m = h4_to_f4(u[j]);
            acc.x = fmaf(v, m.x, acc.x); acc.y = fmaf(v, m.y, acc.y);
            acc.z = fmaf(v, m.z, acc.z); acc.w = fmaf(v, m.w, acc.w);
        }
    }
    if (e + 4 <= e1) {
        uint2 cv[4]; uint2 u[4];
        #pragma unroll
        for (int j = 0; j < 4; j++) cv[j] = g_csr[e + j];
        #pragma unroll
        for (int j = 0; j < 4; j++) u[j] = XWv[cv[j].x * 32 + lane];
        #pragma unroll
        for (int j = 0; j < 4; j++) {
            float v = __uint_as_float(cv[j].y);
            float4 m = h4_to_f4(u[j]);
            acc.x = fmaf(v, m.x, acc.x); acc.y = fmaf(v, m.y, acc.y);
            acc.z = fmaf(v, m.z, acc.z); acc.w = fmaf(v, m.w, acc.w);
        }
        e += 4;
    }
    for (; e < e1; e++) {
        uint2 cv = g_csr[e];
        float v = __uint_as_float(cv.y);
        float4 m = h4_to_f4(XWv[cv.x * 32 + lane]);
        acc.x = fmaf(v, m.x, acc.x); acc.y = fmaf(v, m.y, acc.y);
        acc.z = fmaf(v, m.z, acc.z); acc.w = fmaf(v, m.w, acc.w);
    }
    float4 b = reinterpret_cast<const float4*>(bias)[lane];
    acc.x = fmaf(acc.x, di, b.x); acc.y = fmaf(acc.y, di, b.y);
    acc.z = fmaf(acc.z, di, b.z); acc.w = fmaf(acc.w, di, b.w);
    if (relu) {
        acc.x = fmaxf(acc.x, 0.f); acc.y = fmaxf(acc.y, 0.f);
        acc.z = fmaxf(acc.z, 0.f); acc.w = fmaxf(acc.w, 0.f);
    }
    if (HALF_OUT) {
        uint2 o;
        __half2 h0 = __floats2half2_rn(acc.x, acc.y);
        __half2 h1 = __floats2half2_rn(acc.z, acc.w);
        o.x = *reinterpret_cast<unsigned*>(&h0);
        o.y = *reinterpret_cast<unsigned*>(&h1);
        reinterpret_cast<uint2*>(OUTv)[node * 32 + lane] = o;
    } else {
        reinterpret_cast<float4*>(OUTv)[node * 32 + lane] = acc;
    }
}

// -------- global mean pool: one block (1024 thr) per graph, fused bounds ----
__global__ void __launch_bounds__(1024) k_pool(const float4* __restrict__ h,
                                               const int* __restrict__ batch,
                                               int n, float4* __restrict__ out) {
    __shared__ float4 part[32][32];
    __shared__ int sse[2];
    int g = blockIdx.x;
    if (threadIdx.x < 2) {
        int target = g + threadIdx.x;
        int lo = 0, hi = n;
        while (lo < hi) {
            int mid = (lo + hi) >> 1;
            if (batch[mid] < target) lo = mid + 1; else hi = mid;
        }
        sse[threadIdx.x] = lo;
    }
    __syncthreads();
    int s = sse[0], e = sse[1];
    int rg = threadIdx.x >> 5;
    int ch = threadIdx.x & 31;
    float4 acc = make_float4(0.f, 0.f, 0.f, 0.f);
    for (int i = s + rg; i < e; i += 32) {
        float4 v = h[i * 32 + ch];
        acc.x += v.x; acc.y += v.y; acc.z += v.z; acc.w += v.w;
    }
    part[rg][ch] = acc;
    __syncthreads();
    #pragma unroll
    for (int off = 16; off > 0; off >>= 1) {
        if (rg < off) {
            float4 o = part[rg + off][ch];
            float4 m = part[rg][ch];
            m.x += o.x; m.y += o.y; m.z += o.z; m.w += o.w;
            part[rg][ch] = m;
        }
        __syncthreads();
    }
    if (rg == 0) {
        float inv = 1.0f / (float)((e - s) > 0 ? (e - s) : 1);
        float4 m = part[0][ch];
        m.x *= inv; m.y *= inv; m.z *= inv; m.w *= inv;
        out[g * 32 + ch] = m;
    }
}

extern "C" void kernel_launch(void* const* d_in, const int* in_sizes, int n_in,
                              void* d_out, int out_size) {
    const float* x     = (const float*)d_in[0];
    const int*   ei    = (const int*)d_in[1];
    const float* ew    = (const float*)d_in[2];
    const int*   batch = (const int*)d_in[3];
    const float* W0    = (const float*)d_in[4];
    const float* b0    = (const float*)d_in[5];
    const float* W1    = (const float*)d_in[6];
    const float* b1    = (const float*)d_in[7];
    const float* W2    = (const float*)d_in[8];
    const float* b2    = (const float*)d_in[9];

    int n = in_sizes[0] / ND;
    int E = in_sizes[1] / 2;
    int ngraphs = out_size / ND;
    const int* src = ei;
    const int* dst = ei + E;

    float  *bufA;
    __half *bufH, *bufH2;
    cudaGetSymbolAddress((void**)&bufA,  g_bufA);
    cudaGetSymbolAddress((void**)&bufH,  g_bufH);
    cudaGetSymbolAddress((void**)&bufH2, g_bufH2);

    int eb  = (E + 255) / 256;
    int gb  = (n + 127) / 128;
    int ab  = (int)(((long long)n * 32 + 255) / 256);
    int sbk = (n + SCANB - 1) / SCANB;

    // normalization + CSR build (g_deg/g_cnt zeroed by protocol)
    k_deg<<<eb, 256>>>(dst, ew, E);
    k_scanA<<<sbk, SCANB>>>(n);
    k_scanC<<<sbk, SCANB>>>(n);
    k_csr<<<eb, 256>>>(src, dst, ew, E);

    // layer 0 (fp32 in -> fp16 interior)
    k_gemm<false><<<gb, 256>>>(x, W0, bufH, n);
    k_agg<true><<<ab, 256>>>(bufH, b0, bufH2, n, 1);
    // layer 1 (fp16 in/out)
    k_gemm<true><<<gb, 256>>>(bufH2, W1, bufH, n);
    k_agg<true><<<ab, 256>>>(bufH, b1, bufH2, n, 1);
    // layer 2 (fp16 in -> fp32 out for pooling)
    k_gemm<true><<<gb, 256>>>(bufH2, W2, bufH, n);
    k_agg<false><<<ab, 256>>>(bufH, b2, bufA, n, 0);

    // pooling (bounds fused)
    k_pool<<<ngraphs, 1024>>>((const float4*)bufA, batch, n, (float4*)d_out);
}